// round 13
// baseline (speedup 1.0000x reference)
#include <cuda_runtime.h>
#include <cuda_fp16.h>
#include <cfloat>
#include <cstdint>

#define B_ 2
#define N_ 2048
#define C_ 1024
#define H_ 16
#define D_ 64

typedef __half h16;

// ---------------------------------------------------------------------------
// Scratch (allocation-free rule: __device__ globals)
// ---------------------------------------------------------------------------
__device__ h16 g_qhi[B_ * H_ * N_ * D_], g_qlo[B_ * H_ * N_ * D_];
__device__ h16 g_khi[B_ * H_ * N_ * D_];
__device__ h16 g_vthi[B_ * H_ * D_ * N_];
__device__ h16 g_xhi[B_ * N_ * C_], g_xlo[B_ * N_ * C_];
__device__ h16 g_wqkvhi[3 * C_ * C_];
__device__ h16 g_wprojhi[C_ * C_];
__device__ h16 g_atthi[B_ * N_ * C_], g_attlo[B_ * N_ * C_];

// ---------------------------------------------------------------------------
// Family-agnostic PTX helpers
// ---------------------------------------------------------------------------
__device__ __forceinline__ uint32_t smem_u32(const void* p) {
    uint32_t a;
    asm("{ .reg .u64 t; cvta.to.shared.u64 t, %1; cvt.u32.u64 %0, t; }" : "=r"(a) : "l"(p));
    return a;
}
#define CP16(saddr, gptr) \
    asm volatile("cp.async.cg.shared.global [%0], [%1], 16;" ::"r"(saddr), "l"(gptr) : "memory")
#define CP_COMMIT() asm volatile("cp.async.commit_group;" ::: "memory")
#define CP_WAIT0()  asm volatile("cp.async.wait_group 0;" ::: "memory")

__device__ __forceinline__ void mma_f16(float c[4], uint32_t a0, uint32_t a1, uint32_t a2,
                                        uint32_t a3, uint32_t b0, uint32_t b1) {
    asm volatile(
        "mma.sync.aligned.m16n8k16.row.col.f32.f16.f16.f32 "
        "{%0,%1,%2,%3},{%4,%5,%6,%7},{%8,%9},{%0,%1,%2,%3};"
        : "+f"(c[0]), "+f"(c[1]), "+f"(c[2]), "+f"(c[3])
        : "r"(a0), "r"(a1), "r"(a2), "r"(a3), "r"(b0), "r"(b1));
}

__device__ __forceinline__ uint32_t pack_h2(h16 a, h16 b) {
    __half2 t; t.x = a; t.y = b;
    return *(uint32_t*)&t;
}
__device__ __forceinline__ uint32_t pack_hi2(float x, float y) {
    return pack_h2(__float2half_rn(x), __float2half_rn(y));
}
__device__ __forceinline__ void split2h(float x, float y, uint32_t& hp, uint32_t& lp) {
    h16 hx = __float2half_rn(x), hy = __float2half_rn(y);
    hp = pack_h2(hx, hy);
    lp = pack_h2(__float2half_rn(x - __half2float(hx)),
                 __float2half_rn(y - __half2float(hy)));
}

// ---------------------------------------------------------------------------
// 128x128x1024 fp16 2-pass mainloop: (Ahi + Alo) x Bhi.
// 256 threads = 8 warps in 4m x 2n grid; warp tile 32x64.
// Per-thread per-kf fragment traffic: A 64B + B 64B = 128B for 32 MMAs.
// ---------------------------------------------------------------------------
#define PITCH 40
#define CH (128 * PITCH)
#define CHB (CH * 2)
#define DPITCH 132
#define SMEM_GEMM (1024 + 128 * DPITCH * 4)   // 68608 >= 1024 + 6*CHB (62464)

__device__ __forceinline__ void gemm_ml(float acc[2][8][4],
                                        const h16* __restrict__ Ahi,
                                        const h16* __restrict__ Alo,
                                        const h16* __restrict__ Bhi,
                                        int m0, int n0, h16* sa) {
    const int tid = threadIdx.x;
    const int wid = tid >> 5, lane = tid & 31;
    const int wm = wid & 3, wn = wid >> 2;   // 4m x 2n
    const int r = lane >> 2, c4 = lane & 3;
    const int grow = tid >> 1, gcol = (tid & 1) * 16;

    const uint32_t sab = smem_u32(sa);
    const uint32_t so = (uint32_t)(grow * PITCH + gcol) * 2;

    const h16* pAh = Ahi + (size_t)(m0 + grow) * C_ + gcol;
    const h16* pAl = Alo + (size_t)(m0 + grow) * C_ + gcol;
    const h16* pBh = Bhi + (size_t)(n0 + grow) * C_ + gcol;

    {
        CP16(sab + 0 * CHB + so,      pAh);
        CP16(sab + 0 * CHB + so + 16, pAh + 8);
        CP16(sab + 2 * CHB + so,      pAl);
        CP16(sab + 2 * CHB + so + 16, pAl + 8);
        CP16(sab + 4 * CHB + so,      pBh);
        CP16(sab + 4 * CHB + so + 16, pBh + 8);
        CP_COMMIT();
        CP_WAIT0();
    }
    __syncthreads();

    for (int c = 0; c < 32; c++) {
        if (c < 31) {
            const int k0 = (c + 1) * 32;
            const uint32_t nb = (uint32_t)((c + 1) & 1) * CHB;
            CP16(sab + 0 * CHB + nb + so,      pAh + k0);
            CP16(sab + 0 * CHB + nb + so + 16, pAh + k0 + 8);
            CP16(sab + 2 * CHB + nb + so,      pAl + k0);
            CP16(sab + 2 * CHB + nb + so + 16, pAl + k0 + 8);
            CP16(sab + 4 * CHB + nb + so,      pBh + k0);
            CP16(sab + 4 * CHB + nb + so + 16, pBh + k0 + 8);
            CP_COMMIT();
        }
        const int bo = (c & 1) * CH;
        const h16* ah = sa + bo;
        const h16* al = sa + 2 * CH + bo;
        const h16* bh = sa + 4 * CH + bo;
#pragma unroll
        for (int kf = 0; kf < 2; kf++) {
            const int kb = kf * 16 + c4 * 2;
            uint32_t afh[2][4], afl[2][4];
#pragma unroll
            for (int mf = 0; mf < 2; mf++) {
                const int row = wm * 32 + mf * 16 + r;
                afh[mf][0] = *(const uint32_t*)(ah + row * PITCH + kb);
                afh[mf][1] = *(const uint32_t*)(ah + (row + 8) * PITCH + kb);
                afh[mf][2] = *(const uint32_t*)(ah + row * PITCH + kb + 8);
                afh[mf][3] = *(const uint32_t*)(ah + (row + 8) * PITCH + kb + 8);
                afl[mf][0] = *(const uint32_t*)(al + row * PITCH + kb);
                afl[mf][1] = *(const uint32_t*)(al + (row + 8) * PITCH + kb);
                afl[mf][2] = *(const uint32_t*)(al + row * PITCH + kb + 8);
                afl[mf][3] = *(const uint32_t*)(al + (row + 8) * PITCH + kb + 8);
            }
            uint32_t bfh[8][2];
#pragma unroll
            for (int nf = 0; nf < 8; nf++) {
                const int nn = wn * 64 + nf * 8 + r;
                bfh[nf][0] = *(const uint32_t*)(bh + nn * PITCH + kb);
                bfh[nf][1] = *(const uint32_t*)(bh + nn * PITCH + kb + 8);
            }
#pragma unroll
            for (int mf = 0; mf < 2; mf++)
#pragma unroll
                for (int nf = 0; nf < 8; nf++)
                    mma_f16(acc[mf][nf], afh[mf][0], afh[mf][1], afh[mf][2], afh[mf][3],
                            bfh[nf][0], bfh[nf][1]);
#pragma unroll
            for (int mf = 0; mf < 2; mf++)
#pragma unroll
                for (int nf = 0; nf < 8; nf++)
                    mma_f16(acc[mf][nf], afl[mf][0], afl[mf][1], afl[mf][2], afl[mf][3],
                            bfh[nf][0], bfh[nf][1]);
        }
        if (c < 31) CP_WAIT0();
        __syncthreads();
    }
}

// ---------------------------------------------------------------------------
// fp32 -> fp16 split. sel 0 = x (hi+lo); sel 1 = w_qkv (hi); sel 2 = w_proj (hi).
// ---------------------------------------------------------------------------
__global__ __launch_bounds__(256) void conv_kernel(const float* __restrict__ src,
                                                   int sel, int n4) {
    int i = blockIdx.x * 256 + threadIdx.x;
    if (i >= n4) return;
    float4 v = ((const float4*)src)[i];
    if (sel == 0) {
        uint32_t hp[2], lp[2];
        split2h(v.x, v.y, hp[0], lp[0]);
        split2h(v.z, v.w, hp[1], lp[1]);
        *(uint32_t*)(g_xhi + 4 * (size_t)i)     = hp[0];
        *(uint32_t*)(g_xhi + 4 * (size_t)i + 2) = hp[1];
        *(uint32_t*)(g_xlo + 4 * (size_t)i)     = lp[0];
        *(uint32_t*)(g_xlo + 4 * (size_t)i + 2) = lp[1];
    } else {
        h16* hi = (sel == 1) ? g_wqkvhi : g_wprojhi;
        *(uint32_t*)(hi + 4 * (size_t)i)     = pack_hi2(v.x, v.y);
        *(uint32_t*)(hi + 4 * (size_t)i + 2) = pack_hi2(v.z, v.w);
    }
}

// ---------------------------------------------------------------------------
// QKV GEMM + fused per-head LayerNorm + fused V transpose.
// Q out: fp16 hi+lo; K out: fp16 hi; V out: transposed fp16 [b,h,d,key].
// grid (24, 32), 256 threads.
// ---------------------------------------------------------------------------
__global__ __launch_bounds__(256) void qkv_mma_kernel(const float* __restrict__ qg,
                                                      const float* __restrict__ qb,
                                                      const float* __restrict__ kg,
                                                      const float* __restrict__ kb) {
    extern __shared__ char smc[];
    float* sgam = (float*)smc;
    float* sbet = (float*)(smc + 256);
    h16* sa = (h16*)(smc + 1024);

    const int n0 = blockIdx.x * 128, m0 = blockIdx.y * 128;
    const int s = n0 >> 10;
    if (threadIdx.x < 64 && s < 2) {
        const float* gg = (s == 0) ? qg : kg;
        const float* bb = (s == 0) ? qb : kb;
        sgam[threadIdx.x] = gg[threadIdx.x];
        sbet[threadIdx.x] = bb[threadIdx.x];
    }

    float acc[2][8][4];
#pragma unroll
    for (int a = 0; a < 2; a++)
#pragma unroll
        for (int b = 0; b < 8; b++)
#pragma unroll
            for (int cc = 0; cc < 4; cc++) acc[a][b][cc] = 0.f;

    gemm_ml(acc, g_xhi, g_xlo, g_wqkvhi, m0, n0, sa);

    float* Dst = (float*)(smc + 1024);
    const int wid = threadIdx.x >> 5, lane = threadIdx.x & 31;
    const int wm = wid & 3, wn = wid >> 2;
    const int r = lane >> 2, c4 = lane & 3;
#pragma unroll
    for (int mf = 0; mf < 2; mf++)
#pragma unroll
        for (int nf = 0; nf < 8; nf++) {
            const int m = wm * 32 + mf * 16 + r;
            const int n = wn * 64 + nf * 8 + c4 * 2;
            *(float2*)&Dst[m * DPITCH + n]       = make_float2(acc[mf][nf][0], acc[mf][nf][1]);
            *(float2*)&Dst[(m + 8) * DPITCH + n] = make_float2(acc[mf][nf][2], acc[mf][nf][3]);
        }
    __syncthreads();

    const int bidx = m0 >> 11, nq0 = m0 & 2047;
    const int h0 = (n0 & 1023) >> 6;

    if (s < 2) {
        // per-(row, head) LayerNorm + split-fp16 (Q) / fp16 (K) store
        const int m = threadIdx.x >> 1, hc = threadIdx.x & 1;
        const float* rowp = Dst + m * DPITCH + hc * 64;
        float f[64];
#pragma unroll
        for (int i = 0; i < 64; i++) f[i] = rowp[i];
        const int nq = nq0 + m;
        const size_t base = (((size_t)(bidx * H_ + h0 + hc)) * N_ + nq) * D_;
        float sum = 0.f;
#pragma unroll
        for (int i = 0; i < 64; i++) sum += f[i];
        float mu = sum * (1.0f / 64.0f);
        float vs = 0.f;
#pragma unroll
        for (int i = 0; i < 64; i++) { float d = f[i] - mu; vs += d * d; }
        float rs = rsqrtf(vs * (1.0f / 64.0f) + 1e-5f);
#pragma unroll
        for (int i = 0; i < 64; i++) f[i] = (f[i] - mu) * rs * sgam[i] + sbet[i];
        if (s == 0) {
#pragma unroll
            for (int i = 0; i < 64; i += 2) {
                uint32_t hp, lp;
                split2h(f[i], f[i + 1], hp, lp);
                *(uint32_t*)(g_qhi + base + i) = hp;
                *(uint32_t*)(g_qlo + base + i) = lp;
            }
        } else {
#pragma unroll
            for (int i = 0; i < 64; i += 2)
                *(uint32_t*)(g_khi + base + i) = pack_hi2(f[i], f[i + 1]);
        }
    } else {
        // fused V transpose: Dst[key][hc*64+d] -> g_vthi[b,h,d,key] (fp16)
        const int col = threadIdx.x & 127;          // hc*64 + d
        const int hc = col >> 6, d = col & 63;
        const int kh = threadIdx.x >> 7;            // key half (0/1)
        h16* dst = g_vthi + ((size_t)(bidx * H_ + h0 + hc)) * D_ * N_ +
                   (size_t)d * N_ + nq0 + kh * 64;
#pragma unroll
        for (int i = 0; i < 64; i += 2) {
            float f0 = Dst[(kh * 64 + i) * DPITCH + col];
            float f1 = Dst[(kh * 64 + i + 1) * DPITCH + col];
            *(uint32_t*)(dst + i) = pack_hi2(f0, f1);
        }
    }
}

// ---------------------------------------------------------------------------
// Flash attention, fp16 2-pass: S = (Qhi+Qlo)·Kh,  O += (Phi+Plo)·Vh.
// 128 threads = 4 warps; warp = 32 q-rows (2 m-frags); Bc = 64 keys/iter.
// Both Q-hi and Q-lo fragments live in registers for the whole kernel.
// SMEM: 2 buffers x (Kh, Vh) x KT halves. Q staged transiently in both buffers.
// ---------------------------------------------------------------------------
#define FP 72
#define KT (64 * FP)                       // 4608 halves per array
#define SMEM_FLASH (4 * KT * 2)            // 36864 bytes

__global__ __launch_bounds__(128) void flash_mma_kernel(const unsigned char* __restrict__ mask) {
    extern __shared__ char smc[];
    h16* sh = (h16*)smc;
    const uint32_t shb = smem_u32(sh);

    const int qt = blockIdx.x, h = blockIdx.y, b = blockIdx.z;
    const int tid = threadIdx.x, wid = tid >> 5, lane = tid & 31;
    const int r = lane >> 2, c4 = lane & 3;
    const int wrow = wid * 32;
    const size_t qkoff = ((size_t)(b * H_ + h)) * N_ * D_;
    const size_t vtoff = ((size_t)(b * H_ + h)) * D_ * N_;

    // ---- stage Q: hi -> buf0 area (2*KT halves), lo -> buf1 area ----
    {
        const h16* qh = g_qhi + qkoff + (size_t)(qt * 128) * D_;
        const h16* ql = g_qlo + qkoff + (size_t)(qt * 128) * D_;
#pragma unroll
        for (int j = 0; j < 8; j++) {
            int id = tid + j * 128;
            int row = id >> 3, c8 = (id & 7) * 8;
            CP16(shb + (row * FP + c8) * 2,              qh + row * D_ + c8);
            CP16(shb + (2 * KT + row * FP + c8) * 2,     ql + row * D_ + c8);
        }
        CP_COMMIT(); CP_WAIT0();
    }
    __syncthreads();

    // ---- Q hi+lo fragments to registers (2 m-frags x 4 k-chunks each) ----
    uint32_t aQh[2][4][4], aQl[2][4][4];
#pragma unroll
    for (int mf = 0; mf < 2; mf++)
#pragma unroll
        for (int kc = 0; kc < 4; kc++) {
            const int ba = (wrow + mf * 16 + r) * FP + kc * 16 + c4 * 2;
            aQh[mf][kc][0] = *(const uint32_t*)(sh + ba);
            aQh[mf][kc][1] = *(const uint32_t*)(sh + ba + 8 * FP);
            aQh[mf][kc][2] = *(const uint32_t*)(sh + ba + 8);
            aQh[mf][kc][3] = *(const uint32_t*)(sh + ba + 8 * FP + 8);
            aQl[mf][kc][0] = *(const uint32_t*)(sh + 2 * KT + ba);
            aQl[mf][kc][1] = *(const uint32_t*)(sh + 2 * KT + ba + 8 * FP);
            aQl[mf][kc][2] = *(const uint32_t*)(sh + 2 * KT + ba + 8);
            aQl[mf][kc][3] = *(const uint32_t*)(sh + 2 * KT + ba + 8 * FP + 8);
        }
    __syncthreads();   // all warps done reading Q before buffers are reused

    auto issue_tile = [&](int kt2, int buf) {
        const uint32_t bo = (uint32_t)(buf * 2 * KT) * 2;
        const h16* kh = g_khi + qkoff + (size_t)(kt2 * 64) * D_;
        const h16* vh = g_vthi + vtoff + kt2 * 64;
#pragma unroll
        for (int j = 0; j < 4; j++) {
            int id = tid + j * 128;
            int row = id >> 3, c8 = (id & 7) * 8;
            uint32_t sd = bo + (row * FP + c8) * 2;
            CP16(shb + sd,          kh + row * D_ + c8);
            CP16(shb + sd + KT * 2, vh + (size_t)row * N_ + c8);
        }
        CP_COMMIT();
    };
    issue_tile(0, 0);
    CP_WAIT0();
    __syncthreads();

    float of[2][8][4];
#pragma unroll
    for (int mf = 0; mf < 2; mf++)
#pragma unroll
        for (int nb = 0; nb < 8; nb++)
#pragma unroll
            for (int k = 0; k < 4; k++) of[mf][nb][k] = 0.f;
    float mI[2][2], lI[2][2];
#pragma unroll
    for (int mf = 0; mf < 2; mf++) {
        mI[mf][0] = mI[mf][1] = -FLT_MAX;
        lI[mf][0] = lI[mf][1] = 0.f;
    }

    const unsigned char* mb[2];
    mb[0] = mask + ((size_t)b * N_ + qt * 128 + wrow + r) * N_;
    mb[1] = mb[0] + 16 * (size_t)N_;
    const float scale = 0.125f;

    for (int kt2 = 0; kt2 < N_ / 64; kt2++) {
        if (kt2 < N_ / 64 - 1) issue_tile(kt2 + 1, (kt2 + 1) & 1);

        const h16* sKh = sh + (kt2 & 1) * 2 * KT;
        const h16* sVh = sKh + KT;

        // ---- S = (Qhi + Qlo) Kh ----
        float sf[2][8][4];
#pragma unroll
        for (int mf = 0; mf < 2; mf++)
#pragma unroll
            for (int nb = 0; nb < 8; nb++)
                sf[mf][nb][0] = sf[mf][nb][1] = sf[mf][nb][2] = sf[mf][nb][3] = 0.f;

#pragma unroll
        for (int kc = 0; kc < 4; kc++) {
#pragma unroll
            for (int g = 0; g < 2; g++) {
                uint32_t kh0[4], kh1[4];
#pragma unroll
                for (int j = 0; j < 4; j++) {
                    const int kb = ((g * 4 + j) * 8 + r) * FP + kc * 16 + c4 * 2;
                    kh0[j] = *(const uint32_t*)(sKh + kb);
                    kh1[j] = *(const uint32_t*)(sKh + kb + 8);
                }
#pragma unroll
                for (int mf = 0; mf < 2; mf++) {
#pragma unroll
                    for (int j = 0; j < 4; j++)
                        mma_f16(sf[mf][g * 4 + j], aQh[mf][kc][0], aQh[mf][kc][1],
                                aQh[mf][kc][2], aQh[mf][kc][3], kh0[j], kh1[j]);
#pragma unroll
                    for (int j = 0; j < 4; j++)
                        mma_f16(sf[mf][g * 4 + j], aQl[mf][kc][0], aQl[mf][kc][1],
                                aQl[mf][kc][2], aQl[mf][kc][3], kh0[j], kh1[j]);
                }
            }
        }

        // ---- scale + mask + online softmax ----
#pragma unroll
        for (int mf = 0; mf < 2; mf++) {
            const unsigned char* mr0 = mb[mf] + kt2 * 64 + c4 * 2;
#pragma unroll
            for (int nb = 0; nb < 8; nb++) {
                uchar2 k0 = *(const uchar2*)(mr0 + nb * 8);
                uchar2 k8 = *(const uchar2*)(mr0 + 8 * N_ + nb * 8);
                sf[mf][nb][0] = k0.x ? -FLT_MAX : sf[mf][nb][0] * scale;
                sf[mf][nb][1] = k0.y ? -FLT_MAX : sf[mf][nb][1] * scale;
                sf[mf][nb][2] = k8.x ? -FLT_MAX : sf[mf][nb][2] * scale;
                sf[mf][nb][3] = k8.y ? -FLT_MAX : sf[mf][nb][3] * scale;
            }
            float mx0 = -FLT_MAX, mx1 = -FLT_MAX;
#pragma unroll
            for (int nb = 0; nb < 8; nb++) {
                mx0 = fmaxf(mx0, fmaxf(sf[mf][nb][0], sf[mf][nb][1]));
                mx1 = fmaxf(mx1, fmaxf(sf[mf][nb][2], sf[mf][nb][3]));
            }
            mx0 = fmaxf(mx0, __shfl_xor_sync(0xffffffffu, mx0, 1));
            mx0 = fmaxf(mx0, __shfl_xor_sync(0xffffffffu, mx0, 2));
            mx1 = fmaxf(mx1, __shfl_xor_sync(0xffffffffu, mx1, 1));
            mx1 = fmaxf(mx1, __shfl_xor_sync(0xffffffffu, mx1, 2));
            const float mn0 = fmaxf(mI[mf][0], mx0), mn1 = fmaxf(mI[mf][1], mx1);
            const float cor0 = __expf(mI[mf][0] - mn0), cor1 = __expf(mI[mf][1] - mn1);
            mI[mf][0] = mn0; mI[mf][1] = mn1;
            float rs0 = 0.f, rs1 = 0.f;
#pragma unroll
            for (int nb = 0; nb < 8; nb++) {
                sf[mf][nb][0] = __expf(sf[mf][nb][0] - mn0);
                sf[mf][nb][1] = __expf(sf[mf][nb][1] - mn0);
                sf[mf][nb][2] = __expf(sf[mf][nb][2] - mn1);
                sf[mf][nb][3] = __expf(sf[mf][nb][3] - mn1);
                rs0 += sf[mf][nb][0] + sf[mf][nb][1];
                rs1 += sf[mf][nb][2] + sf[mf][nb][3];
            }
            rs0 += __shfl_xor_sync(0xffffffffu, rs0, 1);
            rs0 += __shfl_xor_sync(0xffffffffu, rs0, 2);
            rs1 += __shfl_xor_sync(0xffffffffu, rs1, 1);
            rs1 += __shfl_xor_sync(0xffffffffu, rs1, 2);
            lI[mf][0] = lI[mf][0] * cor0 + rs0;
            lI[mf][1] = lI[mf][1] * cor1 + rs1;
#pragma unroll
            for (int nb = 0; nb < 8; nb++) {
                of[mf][nb][0] *= cor0; of[mf][nb][1] *= cor0;
                of[mf][nb][2] *= cor1; of[mf][nb][3] *= cor1;
            }
        }

        // ---- O += (Phi + Plo) Vh ----
#pragma unroll
        for (int kc = 0; kc < 4; kc++) {
            uint32_t ph[2][4], pl[2][4];
#pragma unroll
            for (int mf = 0; mf < 2; mf++) {
                split2h(sf[mf][2 * kc][0], sf[mf][2 * kc][1], ph[mf][0], pl[mf][0]);
                split2h(sf[mf][2 * kc][2], sf[mf][2 * kc][3], ph[mf][1], pl[mf][1]);
                split2h(sf[mf][2 * kc + 1][0], sf[mf][2 * kc + 1][1], ph[mf][2], pl[mf][2]);
                split2h(sf[mf][2 * kc + 1][2], sf[mf][2 * kc + 1][3], ph[mf][3], pl[mf][3]);
            }
#pragma unroll
            for (int g = 0; g < 2; g++) {
                uint32_t vh0[4], vh1[4];
#pragma unroll
                for (int j = 0; j < 4; j++) {
                    const int vb = ((g * 4 + j) * 8 + r) * FP + kc * 16 + c4 * 2;
                    vh0[j] = *(const uint32_t*)(sVh + vb);
                    vh1[j] = *(const uint32_t*)(sVh + vb + 8);
                }
#pragma unroll
                for (int mf = 0; mf < 2; mf++) {
#pragma unroll
                    for (int j = 0; j < 4; j++)
                        mma_f16(of[mf][g * 4 + j], ph[mf][0], ph[mf][1], ph[mf][2], ph[mf][3],
                                vh0[j], vh1[j]);
#pragma unroll
                    for (int j = 0; j < 4; j++)
                        mma_f16(of[mf][g * 4 + j], pl[mf][0], pl[mf][1], pl[mf][2], pl[mf][3],
                                vh0[j], vh1[j]);
                }
            }
        }

        if (kt2 < N_ / 64 - 1) CP_WAIT0();
        __syncthreads();
    }

    // ---- epilogue: normalize, write split fp16 att [B,N,C] ----
#pragma unroll
    for (int mf = 0; mf < 2; mf++) {
        const float inv0 = 1.0f / lI[mf][0], inv1 = 1.0f / lI[mf][1];
        const int row0 = qt * 128 + wrow + mf * 16 + r;
        const size_t ob0 = ((size_t)b * N_ + row0) * C_ + h * 64 + c4 * 2;
        const size_t ob1 = ob0 + 8 * (size_t)C_;
#pragma unroll
        for (int nb = 0; nb < 8; nb++) {
            uint32_t hp, lp;
            split2h(of[mf][nb][0] * inv0, of[mf][nb][1] * inv0, hp, lp);
            *(uint32_t*)(g_atthi + ob0 + nb * 8) = hp;
            *(uint32_t*)(g_attlo + ob0 + nb * 8) = lp;
            split2h(of[mf][nb][2] * inv1, of[mf][nb][3] * inv1, hp, lp);
            *(uint32_t*)(g_atthi + ob1 + nb * 8) = hp;
            *(uint32_t*)(g_attlo + ob1 + nb * 8) = lp;
        }
    }
}

// ---------------------------------------------------------------------------
// Projection GEMM + bias. grid (8, 32), 256 threads.
// ---------------------------------------------------------------------------
__global__ __launch_bounds__(256) void proj_mma_kernel(const float* __restrict__ bias,
                                                       float* __restrict__ out) {
    extern __shared__ char smc[];
    float* sbias = (float*)smc;
    h16* sa = (h16*)(smc + 1024);
    const int n0 = blockIdx.x * 128, m0 = blockIdx.y * 128;
    if (threadIdx.x < 128) sbias[threadIdx.x] = bias[n0 + threadIdx.x];

    float acc[2][8][4];
#pragma unroll
    for (int a = 0; a < 2; a++)
#pragma unroll
        for (int b = 0; b < 8; b++)
#pragma unroll
            for (int cc = 0; cc < 4; cc++) acc[a][b][cc] = 0.f;

    gemm_ml(acc, g_atthi, g_attlo, g_wprojhi, m0, n0, sa);

    const int wid = threadIdx.x >> 5, lane = threadIdx.x & 31;
    const int wm = wid & 3, wn = wid >> 2;
    const int r = lane >> 2, c4 = lane & 3;
#pragma unroll
    for (int mf = 0; mf < 2; mf++)
#pragma unroll
        for (int nf = 0; nf < 8; nf++) {
            const int m = wm * 32 + mf * 16 + r;
            const int n = wn * 64 + nf * 8 + c4 * 2;
            const float b0 = sbias[n], b1 = sbias[n + 1];
            *(float2*)&out[(size_t)(m0 + m) * C_ + n0 + n] =
                make_float2(acc[mf][nf][0] + b0, acc[mf][nf][1] + b1);
            *(float2*)&out[(size_t)(m0 + m + 8) * C_ + n0 + n] =
                make_float2(acc[mf][nf][2] + b0, acc[mf][nf][3] + b1);
        }
}

// ---------------------------------------------------------------------------
extern "C" void kernel_launch(void* const* d_in, const int* in_sizes, int n_in,
                              void* d_out, int out_size) {
    const float*         x      = (const float*)d_in[0];
    const unsigned char* mask   = (const unsigned char*)d_in[1];
    const float*         w_qkv  = (const float*)d_in[2];
    const float*         w_proj = (const float*)d_in[3];
    const float*         b_proj = (const float*)d_in[4];
    const float*         qg     = (const float*)d_in[5];
    const float*         qb     = (const float*)d_in[6];
    const float*         kg     = (const float*)d_in[7];
    const float*         kb     = (const float*)d_in[8];
    float* out = (float*)d_out;

    conv_kernel<<<4096, 256>>>(x, 0, (B_ * N_ * C_) / 4);
    conv_kernel<<<3072, 256>>>(w_qkv, 1, (3 * C_ * C_) / 4);
    conv_kernel<<<1024, 256>>>(w_proj, 2, (C_ * C_) / 4);

    cudaFuncSetAttribute(qkv_mma_kernel, cudaFuncAttributeMaxDynamicSharedMemorySize, SMEM_GEMM);
    qkv_mma_kernel<<<dim3(24, 32), 256, SMEM_GEMM>>>(qg, qb, kg, kb);

    cudaFuncSetAttribute(flash_mma_kernel, cudaFuncAttributeMaxDynamicSharedMemorySize, SMEM_FLASH);
    flash_mma_kernel<<<dim3(N_ / 128, H_, B_), 128, SMEM_FLASH>>>(mask);

    cudaFuncSetAttribute(proj_mma_kernel, cudaFuncAttributeMaxDynamicSharedMemorySize, SMEM_GEMM);
    proj_mma_kernel<<<dim3(8, 32), 256, SMEM_GEMM>>>(b_proj, out);
}

// round 14
// speedup vs baseline: 1.0220x; 1.0220x over previous
#include <cuda_runtime.h>
#include <cuda_fp16.h>
#include <cfloat>
#include <cstdint>

#define B_ 2
#define N_ 2048
#define C_ 1024
#define H_ 16
#define D_ 64

typedef __half h16;

// ---------------------------------------------------------------------------
// Scratch (allocation-free rule: __device__ globals)
// ---------------------------------------------------------------------------
__device__ h16 g_qhi[B_ * H_ * N_ * D_], g_qlo[B_ * H_ * N_ * D_];
__device__ h16 g_khi[B_ * H_ * N_ * D_];
__device__ h16 g_vthi[B_ * H_ * D_ * N_];
__device__ h16 g_xhi[B_ * N_ * C_], g_xlo[B_ * N_ * C_];
__device__ h16 g_wqkvhi[3 * C_ * C_];
__device__ h16 g_wprojhi[C_ * C_];
__device__ h16 g_atthi[B_ * N_ * C_], g_attlo[B_ * N_ * C_];

// ---------------------------------------------------------------------------
// Family-agnostic PTX helpers
// ---------------------------------------------------------------------------
__device__ __forceinline__ uint32_t smem_u32(const void* p) {
    uint32_t a;
    asm("{ .reg .u64 t; cvta.to.shared.u64 t, %1; cvt.u32.u64 %0, t; }" : "=r"(a) : "l"(p));
    return a;
}
#define CP16(saddr, gptr) \
    asm volatile("cp.async.cg.shared.global [%0], [%1], 16;" ::"r"(saddr), "l"(gptr) : "memory")
#define CP_COMMIT() asm volatile("cp.async.commit_group;" ::: "memory")
#define CP_WAIT0()  asm volatile("cp.async.wait_group 0;" ::: "memory")
#define CP_WAIT1()  asm volatile("cp.async.wait_group 1;" ::: "memory")

__device__ __forceinline__ void mma_f16(float c[4], uint32_t a0, uint32_t a1, uint32_t a2,
                                        uint32_t a3, uint32_t b0, uint32_t b1) {
    asm volatile(
        "mma.sync.aligned.m16n8k16.row.col.f32.f16.f16.f32 "
        "{%0,%1,%2,%3},{%4,%5,%6,%7},{%8,%9},{%0,%1,%2,%3};"
        : "+f"(c[0]), "+f"(c[1]), "+f"(c[2]), "+f"(c[3])
        : "r"(a0), "r"(a1), "r"(a2), "r"(a3), "r"(b0), "r"(b1));
}

__device__ __forceinline__ uint32_t pack_h2(h16 a, h16 b) {
    __half2 t; t.x = a; t.y = b;
    return *(uint32_t*)&t;
}
__device__ __forceinline__ uint32_t pack_hi2(float x, float y) {
    return pack_h2(__float2half_rn(x), __float2half_rn(y));
}
__device__ __forceinline__ void split2h(float x, float y, uint32_t& hp, uint32_t& lp) {
    h16 hx = __float2half_rn(x), hy = __float2half_rn(y);
    hp = pack_h2(hx, hy);
    lp = pack_h2(__float2half_rn(x - __half2float(hx)),
                 __float2half_rn(y - __half2float(hy)));
}

// ---------------------------------------------------------------------------
// 128x128x1024 fp16 2-pass mainloop: (Ahi + Alo) x Bhi.
// 256 threads = 8 warps (2m x 4n), warp tile 64x32, K-chunk 32.
// 3-stage cp.async pipeline, wait_group 1: load latency overlapped by 2 chunks.
// Array-stage layout (halves): (array*3 + stage) * CH;  arrays: 0=Ah 1=Al 2=Bh.
// ---------------------------------------------------------------------------
#define PITCH 40
#define CH (128 * PITCH)          // halves per array-stage
#define SB (CH * 2)               // bytes per array-stage (10240)
#define DPITCH 132
#define SMEM_GEMM (1024 + 9 * SB) // 93184 >= 1024 + 128*DPITCH*4 (68608)

__device__ __forceinline__ void gemm_ml(float acc[4][4][4],
                                        const h16* __restrict__ Ahi,
                                        const h16* __restrict__ Alo,
                                        const h16* __restrict__ Bhi,
                                        int m0, int n0, h16* sa) {
    const int tid = threadIdx.x;
    const int wid = tid >> 5, lane = tid & 31;
    const int wm = wid & 1, wn = wid >> 1;
    const int r = lane >> 2, c4 = lane & 3;
    const int grow = tid >> 1, gcol = (tid & 1) * 16;

    const uint32_t sab = smem_u32(sa);
    const uint32_t so = (uint32_t)(grow * PITCH + gcol) * 2;

    const h16* pAh = Ahi + (size_t)(m0 + grow) * C_ + gcol;
    const h16* pAl = Alo + (size_t)(m0 + grow) * C_ + gcol;
    const h16* pBh = Bhi + (size_t)(n0 + grow) * C_ + gcol;

    auto issue = [&](int c) {
        const uint32_t st = (uint32_t)(c % 3);
        const int k0 = c * 32;
        CP16(sab + (0 * 3 + st) * SB + so,      pAh + k0);
        CP16(sab + (0 * 3 + st) * SB + so + 16, pAh + k0 + 8);
        CP16(sab + (1 * 3 + st) * SB + so,      pAl + k0);
        CP16(sab + (1 * 3 + st) * SB + so + 16, pAl + k0 + 8);
        CP16(sab + (2 * 3 + st) * SB + so,      pBh + k0);
        CP16(sab + (2 * 3 + st) * SB + so + 16, pBh + k0 + 8);
        CP_COMMIT();
    };
    issue(0);
    issue(1);

    for (int c = 0; c < 32; c++) {
        if (c == 31) { CP_WAIT0(); } else { CP_WAIT1(); }   // chunk c resident
        __syncthreads();
        if (c + 2 < 32) issue(c + 2);                       // into stage (c+2)%3

        const int st = c % 3;
        const h16* ah = sa + (0 * 3 + st) * CH;
        const h16* al = sa + (1 * 3 + st) * CH;
        const h16* bh = sa + (2 * 3 + st) * CH;
#pragma unroll
        for (int kf = 0; kf < 2; kf++) {
            const int kb = kf * 16 + c4 * 2;
            uint32_t afh[4][4], afl[4][4];
#pragma unroll
            for (int mf = 0; mf < 4; mf++) {
                const int row = wm * 64 + mf * 16 + r;
                afh[mf][0] = *(const uint32_t*)(ah + row * PITCH + kb);
                afh[mf][1] = *(const uint32_t*)(ah + (row + 8) * PITCH + kb);
                afh[mf][2] = *(const uint32_t*)(ah + row * PITCH + kb + 8);
                afh[mf][3] = *(const uint32_t*)(ah + (row + 8) * PITCH + kb + 8);
                afl[mf][0] = *(const uint32_t*)(al + row * PITCH + kb);
                afl[mf][1] = *(const uint32_t*)(al + (row + 8) * PITCH + kb);
                afl[mf][2] = *(const uint32_t*)(al + row * PITCH + kb + 8);
                afl[mf][3] = *(const uint32_t*)(al + (row + 8) * PITCH + kb + 8);
            }
            uint32_t bfh[4][2];
#pragma unroll
            for (int nf = 0; nf < 4; nf++) {
                const int nn = wn * 32 + nf * 8 + r;
                bfh[nf][0] = *(const uint32_t*)(bh + nn * PITCH + kb);
                bfh[nf][1] = *(const uint32_t*)(bh + nn * PITCH + kb + 8);
            }
#pragma unroll
            for (int mf = 0; mf < 4; mf++)
#pragma unroll
                for (int nf = 0; nf < 4; nf++)
                    mma_f16(acc[mf][nf], afh[mf][0], afh[mf][1], afh[mf][2], afh[mf][3],
                            bfh[nf][0], bfh[nf][1]);
#pragma unroll
            for (int mf = 0; mf < 4; mf++)
#pragma unroll
                for (int nf = 0; nf < 4; nf++)
                    mma_f16(acc[mf][nf], afl[mf][0], afl[mf][1], afl[mf][2], afl[mf][3],
                            bfh[nf][0], bfh[nf][1]);
        }
        __syncthreads();
    }
}

// ---------------------------------------------------------------------------
// fp32 -> fp16 split. sel 0 = x (hi+lo); sel 1 = w_qkv (hi); sel 2 = w_proj (hi).
// ---------------------------------------------------------------------------
__global__ __launch_bounds__(256) void conv_kernel(const float* __restrict__ src,
                                                   int sel, int n4) {
    int i = blockIdx.x * 256 + threadIdx.x;
    if (i >= n4) return;
    float4 v = ((const float4*)src)[i];
    if (sel == 0) {
        uint32_t hp[2], lp[2];
        split2h(v.x, v.y, hp[0], lp[0]);
        split2h(v.z, v.w, hp[1], lp[1]);
        *(uint32_t*)(g_xhi + 4 * (size_t)i)     = hp[0];
        *(uint32_t*)(g_xhi + 4 * (size_t)i + 2) = hp[1];
        *(uint32_t*)(g_xlo + 4 * (size_t)i)     = lp[0];
        *(uint32_t*)(g_xlo + 4 * (size_t)i + 2) = lp[1];
    } else {
        h16* hi = (sel == 1) ? g_wqkvhi : g_wprojhi;
        *(uint32_t*)(hi + 4 * (size_t)i)     = pack_hi2(v.x, v.y);
        *(uint32_t*)(hi + 4 * (size_t)i + 2) = pack_hi2(v.z, v.w);
    }
}

// ---------------------------------------------------------------------------
// QKV GEMM + fused per-head LayerNorm + fused V transpose.
// Q out: fp16 hi+lo; K out: fp16 hi; V out: transposed fp16 [b,h,d,key].
// grid (24, 32), 256 threads.
// ---------------------------------------------------------------------------
__global__ __launch_bounds__(256) void qkv_mma_kernel(const float* __restrict__ qg,
                                                      const float* __restrict__ qb,
                                                      const float* __restrict__ kg,
                                                      const float* __restrict__ kb) {
    extern __shared__ char smc[];
    float* sgam = (float*)smc;
    float* sbet = (float*)(smc + 256);
    h16* sa = (h16*)(smc + 1024);

    const int n0 = blockIdx.x * 128, m0 = blockIdx.y * 128;
    const int s = n0 >> 10;
    if (threadIdx.x < 64 && s < 2) {
        const float* gg = (s == 0) ? qg : kg;
        const float* bb = (s == 0) ? qb : kb;
        sgam[threadIdx.x] = gg[threadIdx.x];
        sbet[threadIdx.x] = bb[threadIdx.x];
    }

    float acc[4][4][4];
#pragma unroll
    for (int a = 0; a < 4; a++)
#pragma unroll
        for (int b = 0; b < 4; b++)
#pragma unroll
            for (int cc = 0; cc < 4; cc++) acc[a][b][cc] = 0.f;

    gemm_ml(acc, g_xhi, g_xlo, g_wqkvhi, m0, n0, sa);

    float* Dst = (float*)(smc + 1024);
    const int wid = threadIdx.x >> 5, lane = threadIdx.x & 31;
    const int wm = wid & 1, wn = wid >> 1;
    const int r = lane >> 2, c4 = lane & 3;
#pragma unroll
    for (int mf = 0; mf < 4; mf++)
#pragma unroll
        for (int nf = 0; nf < 4; nf++) {
            const int m = wm * 64 + mf * 16 + r;
            const int n = wn * 32 + nf * 8 + c4 * 2;
            *(float2*)&Dst[m * DPITCH + n]       = make_float2(acc[mf][nf][0], acc[mf][nf][1]);
            *(float2*)&Dst[(m + 8) * DPITCH + n] = make_float2(acc[mf][nf][2], acc[mf][nf][3]);
        }
    __syncthreads();

    const int bidx = m0 >> 11, nq0 = m0 & 2047;
    const int h0 = (n0 & 1023) >> 6;

    if (s < 2) {
        // per-(row, head) LayerNorm + split-fp16 (Q) / fp16 (K) store
        const int m = threadIdx.x >> 1, hc = threadIdx.x & 1;
        const float* rowp = Dst + m * DPITCH + hc * 64;
        float f[64];
#pragma unroll
        for (int i = 0; i < 64; i++) f[i] = rowp[i];
        const int nq = nq0 + m;
        const size_t base = (((size_t)(bidx * H_ + h0 + hc)) * N_ + nq) * D_;
        float sum = 0.f;
#pragma unroll
        for (int i = 0; i < 64; i++) sum += f[i];
        float mu = sum * (1.0f / 64.0f);
        float vs = 0.f;
#pragma unroll
        for (int i = 0; i < 64; i++) { float d = f[i] - mu; vs += d * d; }
        float rs = rsqrtf(vs * (1.0f / 64.0f) + 1e-5f);
#pragma unroll
        for (int i = 0; i < 64; i++) f[i] = (f[i] - mu) * rs * sgam[i] + sbet[i];
        if (s == 0) {
#pragma unroll
            for (int i = 0; i < 64; i += 2) {
                uint32_t hp, lp;
                split2h(f[i], f[i + 1], hp, lp);
                *(uint32_t*)(g_qhi + base + i) = hp;
                *(uint32_t*)(g_qlo + base + i) = lp;
            }
        } else {
#pragma unroll
            for (int i = 0; i < 64; i += 2)
                *(uint32_t*)(g_khi + base + i) = pack_hi2(f[i], f[i + 1]);
        }
    } else {
        // fused V transpose: Dst[key][hc*64+d] -> g_vthi[b,h,d,key] (fp16)
        const int col = threadIdx.x & 127;          // hc*64 + d
        const int hc = col >> 6, d = col & 63;
        const int kh = threadIdx.x >> 7;            // key half (0/1)
        h16* dst = g_vthi + ((size_t)(bidx * H_ + h0 + hc)) * D_ * N_ +
                   (size_t)d * N_ + nq0 + kh * 64;
#pragma unroll
        for (int i = 0; i < 64; i += 2) {
            float f0 = Dst[(kh * 64 + i) * DPITCH + col];
            float f1 = Dst[(kh * 64 + i + 1) * DPITCH + col];
            *(uint32_t*)(dst + i) = pack_hi2(f0, f1);
        }
    }
}

// ---------------------------------------------------------------------------
// Flash attention, fp16 2-pass: S = (Qhi+Qlo)·Kh,  O += (Phi+Plo)·Vh.
// 128 threads = 4 warps; warp = 32 q-rows (2 m-frags); Bc = 64 keys/iter.
// Q hi+lo fragments live in registers; 2-buffer K/V pipeline (compute/tile
// is large enough to hide load latency here).
// ---------------------------------------------------------------------------
#define FP 72
#define KT (64 * FP)                       // 4608 halves per array
#define SMEM_FLASH (4 * KT * 2)            // 36864 bytes

__global__ __launch_bounds__(128) void flash_mma_kernel(const unsigned char* __restrict__ mask) {
    extern __shared__ char smc[];
    h16* sh = (h16*)smc;
    const uint32_t shb = smem_u32(sh);

    const int qt = blockIdx.x, h = blockIdx.y, b = blockIdx.z;
    const int tid = threadIdx.x, wid = tid >> 5, lane = tid & 31;
    const int r = lane >> 2, c4 = lane & 3;
    const int wrow = wid * 32;
    const size_t qkoff = ((size_t)(b * H_ + h)) * N_ * D_;
    const size_t vtoff = ((size_t)(b * H_ + h)) * D_ * N_;

    // ---- stage Q: hi -> buf0 area, lo -> buf1 area (transient) ----
    {
        const h16* qh = g_qhi + qkoff + (size_t)(qt * 128) * D_;
        const h16* ql = g_qlo + qkoff + (size_t)(qt * 128) * D_;
#pragma unroll
        for (int j = 0; j < 8; j++) {
            int id = tid + j * 128;
            int row = id >> 3, c8 = (id & 7) * 8;
            CP16(shb + (row * FP + c8) * 2,          qh + row * D_ + c8);
            CP16(shb + (2 * KT + row * FP + c8) * 2, ql + row * D_ + c8);
        }
        CP_COMMIT(); CP_WAIT0();
    }
    __syncthreads();

    // ---- Q hi+lo fragments to registers ----
    uint32_t aQh[2][4][4], aQl[2][4][4];
#pragma unroll
    for (int mf = 0; mf < 2; mf++)
#pragma unroll
        for (int kc = 0; kc < 4; kc++) {
            const int ba = (wrow + mf * 16 + r) * FP + kc * 16 + c4 * 2;
            aQh[mf][kc][0] = *(const uint32_t*)(sh + ba);
            aQh[mf][kc][1] = *(const uint32_t*)(sh + ba + 8 * FP);
            aQh[mf][kc][2] = *(const uint32_t*)(sh + ba + 8);
            aQh[mf][kc][3] = *(const uint32_t*)(sh + ba + 8 * FP + 8);
            aQl[mf][kc][0] = *(const uint32_t*)(sh + 2 * KT + ba);
            aQl[mf][kc][1] = *(const uint32_t*)(sh + 2 * KT + ba + 8 * FP);
            aQl[mf][kc][2] = *(const uint32_t*)(sh + 2 * KT + ba + 8);
            aQl[mf][kc][3] = *(const uint32_t*)(sh + 2 * KT + ba + 8 * FP + 8);
        }
    __syncthreads();

    auto issue_tile = [&](int kt2, int buf) {
        const uint32_t bo = (uint32_t)(buf * 2 * KT) * 2;
        const h16* kh = g_khi + qkoff + (size_t)(kt2 * 64) * D_;
        const h16* vh = g_vthi + vtoff + kt2 * 64;
#pragma unroll
        for (int j = 0; j < 4; j++) {
            int id = tid + j * 128;
            int row = id >> 3, c8 = (id & 7) * 8;
            uint32_t sd = bo + (row * FP + c8) * 2;
            CP16(shb + sd,          kh + row * D_ + c8);
            CP16(shb + sd + KT * 2, vh + (size_t)row * N_ + c8);
        }
        CP_COMMIT();
    };
    issue_tile(0, 0);
    CP_WAIT0();
    __syncthreads();

    float of[2][8][4];
#pragma unroll
    for (int mf = 0; mf < 2; mf++)
#pragma unroll
        for (int nb = 0; nb < 8; nb++)
#pragma unroll
            for (int k = 0; k < 4; k++) of[mf][nb][k] = 0.f;
    float mI[2][2], lI[2][2];
#pragma unroll
    for (int mf = 0; mf < 2; mf++) {
        mI[mf][0] = mI[mf][1] = -FLT_MAX;
        lI[mf][0] = lI[mf][1] = 0.f;
    }

    const unsigned char* mb[2];
    mb[0] = mask + ((size_t)b * N_ + qt * 128 + wrow + r) * N_;
    mb[1] = mb[0] + 16 * (size_t)N_;
    const float scale = 0.125f;

    for (int kt2 = 0; kt2 < N_ / 64; kt2++) {
        if (kt2 < N_ / 64 - 1) issue_tile(kt2 + 1, (kt2 + 1) & 1);

        const h16* sKh = sh + (kt2 & 1) * 2 * KT;
        const h16* sVh = sKh + KT;

        // ---- S = (Qhi + Qlo) Kh ----
        float sf[2][8][4];
#pragma unroll
        for (int mf = 0; mf < 2; mf++)
#pragma unroll
            for (int nb = 0; nb < 8; nb++)
                sf[mf][nb][0] = sf[mf][nb][1] = sf[mf][nb][2] = sf[mf][nb][3] = 0.f;

#pragma unroll
        for (int kc = 0; kc < 4; kc++) {
#pragma unroll
            for (int g = 0; g < 2; g++) {
                uint32_t kh0[4], kh1[4];
#pragma unroll
                for (int j = 0; j < 4; j++) {
                    const int kb = ((g * 4 + j) * 8 + r) * FP + kc * 16 + c4 * 2;
                    kh0[j] = *(const uint32_t*)(sKh + kb);
                    kh1[j] = *(const uint32_t*)(sKh + kb + 8);
                }
#pragma unroll
                for (int mf = 0; mf < 2; mf++) {
#pragma unroll
                    for (int j = 0; j < 4; j++)
                        mma_f16(sf[mf][g * 4 + j], aQh[mf][kc][0], aQh[mf][kc][1],
                                aQh[mf][kc][2], aQh[mf][kc][3], kh0[j], kh1[j]);
#pragma unroll
                    for (int j = 0; j < 4; j++)
                        mma_f16(sf[mf][g * 4 + j], aQl[mf][kc][0], aQl[mf][kc][1],
                                aQl[mf][kc][2], aQl[mf][kc][3], kh0[j], kh1[j]);
                }
            }
        }

        // ---- scale + mask + online softmax ----
#pragma unroll
        for (int mf = 0; mf < 2; mf++) {
            const unsigned char* mr0 = mb[mf] + kt2 * 64 + c4 * 2;
#pragma unroll
            for (int nb = 0; nb < 8; nb++) {
                uchar2 k0 = *(const uchar2*)(mr0 + nb * 8);
                uchar2 k8 = *(const uchar2*)(mr0 + 8 * N_ + nb * 8);
                sf[mf][nb][0] = k0.x ? -FLT_MAX : sf[mf][nb][0] * scale;
                sf[mf][nb][1] = k0.y ? -FLT_MAX : sf[mf][nb][1] * scale;
                sf[mf][nb][2] = k8.x ? -FLT_MAX : sf[mf][nb][2] * scale;
                sf[mf][nb][3] = k8.y ? -FLT_MAX : sf[mf][nb][3] * scale;
            }
            float mx0 = -FLT_MAX, mx1 = -FLT_MAX;
#pragma unroll
            for (int nb = 0; nb < 8; nb++) {
                mx0 = fmaxf(mx0, fmaxf(sf[mf][nb][0], sf[mf][nb][1]));
                mx1 = fmaxf(mx1, fmaxf(sf[mf][nb][2], sf[mf][nb][3]));
            }
            mx0 = fmaxf(mx0, __shfl_xor_sync(0xffffffffu, mx0, 1));
            mx0 = fmaxf(mx0, __shfl_xor_sync(0xffffffffu, mx0, 2));
            mx1 = fmaxf(mx1, __shfl_xor_sync(0xffffffffu, mx1, 1));
            mx1 = fmaxf(mx1, __shfl_xor_sync(0xffffffffu, mx1, 2));
            const float mn0 = fmaxf(mI[mf][0], mx0), mn1 = fmaxf(mI[mf][1], mx1);
            const float cor0 = __expf(mI[mf][0] - mn0), cor1 = __expf(mI[mf][1] - mn1);
            mI[mf][0] = mn0; mI[mf][1] = mn1;
            float rs0 = 0.f, rs1 = 0.f;
#pragma unroll
            for (int nb = 0; nb < 8; nb++) {
                sf[mf][nb][0] = __expf(sf[mf][nb][0] - mn0);
                sf[mf][nb][1] = __expf(sf[mf][nb][1] - mn0);
                sf[mf][nb][2] = __expf(sf[mf][nb][2] - mn1);
                sf[mf][nb][3] = __expf(sf[mf][nb][3] - mn1);
                rs0 += sf[mf][nb][0] + sf[mf][nb][1];
                rs1 += sf[mf][nb][2] + sf[mf][nb][3];
            }
            rs0 += __shfl_xor_sync(0xffffffffu, rs0, 1);
            rs0 += __shfl_xor_sync(0xffffffffu, rs0, 2);
            rs1 += __shfl_xor_sync(0xffffffffu, rs1, 1);
            rs1 += __shfl_xor_sync(0xffffffffu, rs1, 2);
            lI[mf][0] = lI[mf][0] * cor0 + rs0;
            lI[mf][1] = lI[mf][1] * cor1 + rs1;
#pragma unroll
            for (int nb = 0; nb < 8; nb++) {
                of[mf][nb][0] *= cor0; of[mf][nb][1] *= cor0;
                of[mf][nb][2] *= cor1; of[mf][nb][3] *= cor1;
            }
        }

        // ---- O += (Phi + Plo) Vh ----
#pragma unroll
        for (int kc = 0; kc < 4; kc++) {
            uint32_t ph[2][4], pl[2][4];
#pragma unroll
            for (int mf = 0; mf < 2; mf++) {
                split2h(sf[mf][2 * kc][0], sf[mf][2 * kc][1], ph[mf][0], pl[mf][0]);
                split2h(sf[mf][2 * kc][2], sf[mf][2 * kc][3], ph[mf][1], pl[mf][1]);
                split2h(sf[mf][2 * kc + 1][0], sf[mf][2 * kc + 1][1], ph[mf][2], pl[mf][2]);
                split2h(sf[mf][2 * kc + 1][2], sf[mf][2 * kc + 1][3], ph[mf][3], pl[mf][3]);
            }
#pragma unroll
            for (int g = 0; g < 2; g++) {
                uint32_t vh0[4], vh1[4];
#pragma unroll
                for (int j = 0; j < 4; j++) {
                    const int vb = ((g * 4 + j) * 8 + r) * FP + kc * 16 + c4 * 2;
                    vh0[j] = *(const uint32_t*)(sVh + vb);
                    vh1[j] = *(const uint32_t*)(sVh + vb + 8);
                }
#pragma unroll
                for (int mf = 0; mf < 2; mf++) {
#pragma unroll
                    for (int j = 0; j < 4; j++)
                        mma_f16(of[mf][g * 4 + j], ph[mf][0], ph[mf][1], ph[mf][2], ph[mf][3],
                                vh0[j], vh1[j]);
#pragma unroll
                    for (int j = 0; j < 4; j++)
                        mma_f16(of[mf][g * 4 + j], pl[mf][0], pl[mf][1], pl[mf][2], pl[mf][3],
                                vh0[j], vh1[j]);
                }
            }
        }

        if (kt2 < N_ / 64 - 1) CP_WAIT0();
        __syncthreads();
    }

    // ---- epilogue: normalize, write split fp16 att [B,N,C] ----
#pragma unroll
    for (int mf = 0; mf < 2; mf++) {
        const float inv0 = 1.0f / lI[mf][0], inv1 = 1.0f / lI[mf][1];
        const int row0 = qt * 128 + wrow + mf * 16 + r;
        const size_t ob0 = ((size_t)b * N_ + row0) * C_ + h * 64 + c4 * 2;
        const size_t ob1 = ob0 + 8 * (size_t)C_;
#pragma unroll
        for (int nb = 0; nb < 8; nb++) {
            uint32_t hp, lp;
            split2h(of[mf][nb][0] * inv0, of[mf][nb][1] * inv0, hp, lp);
            *(uint32_t*)(g_atthi + ob0 + nb * 8) = hp;
            *(uint32_t*)(g_attlo + ob0 + nb * 8) = lp;
            split2h(of[mf][nb][2] * inv1, of[mf][nb][3] * inv1, hp, lp);
            *(uint32_t*)(g_atthi + ob1 + nb * 8) = hp;
            *(uint32_t*)(g_attlo + ob1 + nb * 8) = lp;
        }
    }
}

// ---------------------------------------------------------------------------
// Projection GEMM + bias. grid (8, 32), 256 threads.
// ---------------------------------------------------------------------------
__global__ __launch_bounds__(256) void proj_mma_kernel(const float* __restrict__ bias,
                                                       float* __restrict__ out) {
    extern __shared__ char smc[];
    float* sbias = (float*)smc;
    h16* sa = (h16*)(smc + 1024);
    const int n0 = blockIdx.x * 128, m0 = blockIdx.y * 128;
    if (threadIdx.x < 128) sbias[threadIdx.x] = bias[n0 + threadIdx.x];

    float acc[4][4][4];
#pragma unroll
    for (int a = 0; a < 4; a++)
#pragma unroll
        for (int b = 0; b < 4; b++)
#pragma unroll
            for (int cc = 0; cc < 4; cc++) acc[a][b][cc] = 0.f;

    gemm_ml(acc, g_atthi, g_attlo, g_wprojhi, m0, n0, sa);

    const int wid = threadIdx.x >> 5, lane = threadIdx.x & 31;
    const int wm = wid & 1, wn = wid >> 1;
    const int r = lane >> 2, c4 = lane & 3;
#pragma unroll
    for (int mf = 0; mf < 4; mf++)
#pragma unroll
        for (int nf = 0; nf < 4; nf++) {
            const int m = wm * 64 + mf * 16 + r;
            const int n = wn * 32 + nf * 8 + c4 * 2;
            const float b0 = sbias[n], b1 = sbias[n + 1];
            *(float2*)&out[(size_t)(m0 + m) * C_ + n0 + n] =
                make_float2(acc[mf][nf][0] + b0, acc[mf][nf][1] + b1);
            *(float2*)&out[(size_t)(m0 + m + 8) * C_ + n0 + n] =
                make_float2(acc[mf][nf][2] + b0, acc[mf][nf][3] + b1);
        }
}

// ---------------------------------------------------------------------------
extern "C" void kernel_launch(void* const* d_in, const int* in_sizes, int n_in,
                              void* d_out, int out_size) {
    const float*         x      = (const float*)d_in[0];
    const unsigned char* mask   = (const unsigned char*)d_in[1];
    const float*         w_qkv  = (const float*)d_in[2];
    const float*         w_proj = (const float*)d_in[3];
    const float*         b_proj = (const float*)d_in[4];
    const float*         qg     = (const float*)d_in[5];
    const float*         qb     = (const float*)d_in[6];
    const float*         kg     = (const float*)d_in[7];
    const float*         kb     = (const float*)d_in[8];
    float* out = (float*)d_out;

    conv_kernel<<<4096, 256>>>(x, 0, (B_ * N_ * C_) / 4);
    conv_kernel<<<3072, 256>>>(w_qkv, 1, (3 * C_ * C_) / 4);
    conv_kernel<<<1024, 256>>>(w_proj, 2, (C_ * C_) / 4);

    cudaFuncSetAttribute(qkv_mma_kernel, cudaFuncAttributeMaxDynamicSharedMemorySize, SMEM_GEMM);
    qkv_mma_kernel<<<dim3(24, 32), 256, SMEM_GEMM>>>(qg, qb, kg, kb);

    cudaFuncSetAttribute(flash_mma_kernel, cudaFuncAttributeMaxDynamicSharedMemorySize, SMEM_FLASH);
    flash_mma_kernel<<<dim3(N_ / 128, H_, B_), 128, SMEM_FLASH>>>(mask);

    cudaFuncSetAttribute(proj_mma_kernel, cudaFuncAttributeMaxDynamicSharedMemorySize, SMEM_GEMM);
    proj_mma_kernel<<<dim3(8, 32), 256, SMEM_GEMM>>>(b_proj, out);
}